// round 3
// baseline (speedup 1.0000x reference)
#include <cuda_runtime.h>

// ChamferDistanceL1: xyz1 [8,8192,3] f32, xyz2 [8,8192,3] f32 -> scalar f32.
// result = mean_b[ (mean_i sqrt(max(min_j d_ij, EPS)) + mean_j sqrt(max(min_i d_ij, EPS))) / 2 ]
// with d = |x|^2 + |r|^2 - 2 x.r  (same formula as the reference, fp32).
//
// Strategy: fp32-FMA-bound brute force. Per query precompute m = -2x (packed
// f32x2, two queries per register pair) and minimize g = sr - 2 x.r via
// 3x fma.rn.f32x2 per ref per query-pair (FFMA2 = 2x scalar FFMA throughput;
// only reachable via inline PTX). Refs staged in smem duplicated ({r,r}) so
// each ref costs 2x LDS.128 broadcast, zero per-j packing MOVs.
// d_min = g_min + |x|^2, clamped, sqrt'd, block-reduced to per-block partials;
// a 1-block kernel then does a deterministic tree reduction + scaling.

#define BATCH   8
#define NPTS    8192
#define BLOCK   256
#define QPT     4                    // queries per thread (2 packed pairs)
#define QPB     (BLOCK * QPT)        // 1024 queries per block
#define CHUNKS  (NPTS / QPB)         // 8
#define TILE    1024                 // refs per smem tile
#define NTILES  (NPTS / TILE)        // 8
#define GRID    (BATCH * CHUNKS * 2) // 128 blocks (both directions)

typedef unsigned long long ull;

__device__ float g_partials[GRID];   // every slot overwritten each launch

__device__ __forceinline__ ull pack2(float lo, float hi) {
    ull r;
    asm("mov.b64 %0, {%1, %2};" : "=l"(r) : "f"(lo), "f"(hi));
    return r;
}
__device__ __forceinline__ void unpack2(ull v, float& lo, float& hi) {
    asm("mov.b64 {%0, %1}, %2;" : "=f"(lo), "=f"(hi) : "l"(v));
}
__device__ __forceinline__ ull fma2(ull a, ull b, ull c) {
    ull d;
    asm("fma.rn.f32x2 %0, %1, %2, %3;" : "=l"(d) : "l"(a), "l"(b), "l"(c));
    return d;
}

__global__ __launch_bounds__(BLOCK, 1)
void chamfer_min_kernel(const float* __restrict__ x1, const float* __restrict__ x2) {
    const int bx    = blockIdx.x;
    const int dir   = bx >> 6;          // 0: q=x1,r=x2 ; 1: q=x2,r=x1
    const int rem   = bx & 63;
    const int b     = rem >> 3;
    const int chunk = rem & 7;

    const float* __restrict__ q = (dir == 0 ? x1 : x2) + (size_t)b * NPTS * 3;
    const float* __restrict__ r = (dir == 0 ? x2 : x1) + (size_t)b * NPTS * 3;

    __shared__ __align__(16) ull s[TILE * 4];   // {r0,r0},{r1,r1},{r2,r2},{sr,sr}
    __shared__ float red[BLOCK];

    const int t = threadIdx.x;

    // ---- load this block's queries: QPT per thread, block-strided ----
    float sx[QPT];
    float qx[QPT], qy[QPT], qz[QPT];
#pragma unroll
    for (int k = 0; k < QPT; k++) {
        const int qi = chunk * QPB + k * BLOCK + t;
        const float a = q[qi * 3 + 0];
        const float c = q[qi * 3 + 1];
        const float e = q[qi * 3 + 2];
        qx[k] = a; qy[k] = c; qz[k] = e;
        sx[k] = a * a + c * c + e * e;
    }

    // packed -2x per query pair (pair p = queries 2p, 2p+1)
    ull m0[QPT / 2], m1[QPT / 2], m2[QPT / 2];
#pragma unroll
    for (int p = 0; p < QPT / 2; p++) {
        m0[p] = pack2(-2.0f * qx[2 * p], -2.0f * qx[2 * p + 1]);
        m1[p] = pack2(-2.0f * qy[2 * p], -2.0f * qy[2 * p + 1]);
        m2[p] = pack2(-2.0f * qz[2 * p], -2.0f * qz[2 * p + 1]);
    }

    float gmin_lo[QPT / 2], gmin_hi[QPT / 2];
#pragma unroll
    for (int p = 0; p < QPT / 2; p++) { gmin_lo[p] = 3.4e38f; gmin_hi[p] = 3.4e38f; }

    // ---- loop over ref tiles ----
    for (int tile = 0; tile < NTILES; tile++) {
        __syncthreads();   // previous tile fully consumed
        for (int i = t; i < TILE; i += BLOCK) {
            const int ri = tile * TILE + i;
            const float a  = r[ri * 3 + 0];
            const float c  = r[ri * 3 + 1];
            const float e  = r[ri * 3 + 2];
            const float sr = a * a + c * c + e * e;
            s[i * 4 + 0] = pack2(a, a);
            s[i * 4 + 1] = pack2(c, c);
            s[i * 4 + 2] = pack2(e, e);
            s[i * 4 + 3] = pack2(sr, sr);
        }
        __syncthreads();

#pragma unroll 4
        for (int j = 0; j < TILE; j++) {
            const ulonglong2 ab = *reinterpret_cast<const ulonglong2*>(&s[j * 4 + 0]);
            const ulonglong2 cd = *reinterpret_cast<const ulonglong2*>(&s[j * 4 + 2]);
            const ull rr0 = ab.x, rr1 = ab.y, rr2 = cd.x, srr = cd.y;
#pragma unroll
            for (int p = 0; p < QPT / 2; p++) {
                ull g = fma2(m2[p], rr2, srr);
                g = fma2(m1[p], rr1, g);
                g = fma2(m0[p], rr0, g);
                float glo, ghi;
                unpack2(g, glo, ghi);
                gmin_lo[p] = fminf(gmin_lo[p], glo);
                gmin_hi[p] = fminf(gmin_hi[p], ghi);
            }
        }
    }

    // ---- epilogue: recover distances, sqrt, sum ----
    float lsum = 0.0f;
#pragma unroll
    for (int p = 0; p < QPT / 2; p++) {
        float d0 = gmin_lo[p] + sx[2 * p];
        float d1 = gmin_hi[p] + sx[2 * p + 1];
        d0 = fmaxf(d0, 0.0f); d1 = fmaxf(d1, 0.0f);
        d0 = fmaxf(d0, 1e-12f); d1 = fmaxf(d1, 1e-12f);
        lsum += sqrtf(d0) + sqrtf(d1);
    }

    // ---- block tree reduction (deterministic) ----
    red[t] = lsum;
    __syncthreads();
#pragma unroll
    for (int stride = BLOCK / 2; stride > 0; stride >>= 1) {
        if (t < stride) red[t] += red[t + stride];
        __syncthreads();
    }
    if (t == 0) g_partials[bx] = red[0];
}

__global__ void chamfer_reduce_kernel(float* __restrict__ out) {
    __shared__ float red[GRID];
    const int t = threadIdx.x;
    red[t] = g_partials[t];
    __syncthreads();
#pragma unroll
    for (int stride = GRID / 2; stride > 0; stride >>= 1) {
        if (t < stride) red[t] += red[t + stride];
        __syncthreads();
    }
    if (t == 0) out[0] = red[0] * (1.0f / (2.0f * BATCH * NPTS));
}

extern "C" void kernel_launch(void* const* d_in, const int* in_sizes, int n_in,
                              void* d_out, int out_size) {
    const float* x1 = (const float*)d_in[0];
    const float* x2 = (const float*)d_in[1];
    (void)in_sizes; (void)n_in; (void)out_size;

    chamfer_min_kernel<<<GRID, BLOCK>>>(x1, x2);
    chamfer_reduce_kernel<<<1, GRID>>>((float*)d_out);
}

// round 6
// speedup vs baseline: 1.0309x; 1.0309x over previous
#include <cuda_runtime.h>

// ChamferDistanceL1: xyz1 [8,8192,3] f32, xyz2 [8,8192,3] f32 -> scalar f32.
// d = |x|^2 + |r|^2 - 2 x.r  (reference formula, fp32).
//
// V2: BLOCK=512 split into two 256-thread halves. Both halves own the SAME
// 1024 queries; half h scans refs [h*4096, (h+1)*4096) through its own smem
// tile buffer. 16 warps/SM (4/SMSP) doubles latency hiding vs V1 at the same
// GRID=128. Per-query mins from the two halves are combined via smem, then
// sqrt + block tree reduction. Inner math: packed fma.rn.f32x2 (FFMA2),
// 1.5 FFMA2 + 1 FMNMX per (query,ref) update.
// Launch pattern [pad, min, reduce, pad] steers ncu -s 5 onto the min kernel.

#define BATCH   8
#define NPTS    8192
#define BLOCK   512
#define HALF    256
#define QPT     4                    // queries per thread (2 packed pairs)
#define QPB     (HALF * QPT)         // 1024 queries per block
#define CHUNKS  (NPTS / QPB)         // 8
#define TILE    512                  // refs per smem tile (per half)
#define HREFS   (NPTS / 2)           // 4096 refs per half
#define HTILES  (HREFS / TILE)       // 8 tiles per half
#define GRID    (BATCH * CHUNKS * 2) // 128 blocks

typedef unsigned long long ull;

__device__ float g_partials[GRID];   // every slot overwritten each launch

__device__ __forceinline__ ull pack2(float lo, float hi) {
    ull r;
    asm("mov.b64 %0, {%1, %2};" : "=l"(r) : "f"(lo), "f"(hi));
    return r;
}
__device__ __forceinline__ void unpack2(ull v, float& lo, float& hi) {
    asm("mov.b64 {%0, %1}, %2;" : "=f"(lo), "=f"(hi) : "l"(v));
}
__device__ __forceinline__ ull fma2(ull a, ull b, ull c) {
    ull d;
    asm("fma.rn.f32x2 %0, %1, %2, %3;" : "=l"(d) : "l"(a), "l"(b), "l"(c));
    return d;
}

__global__ void chamfer_pad_kernel() { }   // ncu launch-index steering only

__global__ __launch_bounds__(BLOCK, 1)
void chamfer_min_kernel(const float* __restrict__ x1, const float* __restrict__ x2) {
    const int bx    = blockIdx.x;
    const int dir   = bx >> 6;          // 0: q=x1,r=x2 ; 1: q=x2,r=x1
    const int rem   = bx & 63;
    const int b     = rem >> 3;
    const int chunk = rem & 7;

    const float* __restrict__ q = (dir == 0 ? x1 : x2) + (size_t)b * NPTS * 3;
    const float* __restrict__ r = (dir == 0 ? x2 : x1) + (size_t)b * NPTS * 3;

    // two tile buffers (one per half): 2 * 512 * 4 ull = 32 KB
    __shared__ __align__(16) ull s[2 * TILE * 4];
    __shared__ float cross[HALF][4];    // half B's mins -> half A
    __shared__ float red[BLOCK];

    const int t  = threadIdx.x;
    const int h  = t >> 8;              // 0 or 1: which ref-half this thread scans
    const int t2 = t & (HALF - 1);      // lane within half

    // ---- queries: identical set for both halves (owned by t2) ----
    float sx[QPT], qx[QPT], qy[QPT], qz[QPT];
#pragma unroll
    for (int k = 0; k < QPT; k++) {
        const int qi = chunk * QPB + k * HALF + t2;
        const float a = q[qi * 3 + 0];
        const float c = q[qi * 3 + 1];
        const float e = q[qi * 3 + 2];
        qx[k] = a; qy[k] = c; qz[k] = e;
        sx[k] = a * a + c * c + e * e;
    }

    ull m0[QPT / 2], m1[QPT / 2], m2[QPT / 2];
#pragma unroll
    for (int p = 0; p < QPT / 2; p++) {
        m0[p] = pack2(-2.0f * qx[2 * p], -2.0f * qx[2 * p + 1]);
        m1[p] = pack2(-2.0f * qy[2 * p], -2.0f * qy[2 * p + 1]);
        m2[p] = pack2(-2.0f * qz[2 * p], -2.0f * qz[2 * p + 1]);
    }

    float gmin_lo[QPT / 2], gmin_hi[QPT / 2];
#pragma unroll
    for (int p = 0; p < QPT / 2; p++) { gmin_lo[p] = 3.4e38f; gmin_hi[p] = 3.4e38f; }

    ull* const sbuf = s + h * (TILE * 4);
    const int ref_base = h * HREFS;

    // ---- loop over this half's ref tiles ----
    for (int tile = 0; tile < HTILES; tile++) {
        __syncthreads();   // previous tile fully consumed (both halves in lockstep)
        for (int i = t2; i < TILE; i += HALF) {
            const int ri = ref_base + tile * TILE + i;
            const float a  = r[ri * 3 + 0];
            const float c  = r[ri * 3 + 1];
            const float e  = r[ri * 3 + 2];
            const float sr = a * a + c * c + e * e;
            sbuf[i * 4 + 0] = pack2(a, a);
            sbuf[i * 4 + 1] = pack2(c, c);
            sbuf[i * 4 + 2] = pack2(e, e);
            sbuf[i * 4 + 3] = pack2(sr, sr);
        }
        __syncthreads();

#pragma unroll 4
        for (int j = 0; j < TILE; j++) {
            const ulonglong2 ab = *reinterpret_cast<const ulonglong2*>(&sbuf[j * 4 + 0]);
            const ulonglong2 cd = *reinterpret_cast<const ulonglong2*>(&sbuf[j * 4 + 2]);
            const ull rr0 = ab.x, rr1 = ab.y, rr2 = cd.x, srr = cd.y;
#pragma unroll
            for (int p = 0; p < QPT / 2; p++) {
                ull g = fma2(m2[p], rr2, srr);
                g = fma2(m1[p], rr1, g);
                g = fma2(m0[p], rr0, g);
                float glo, ghi;
                unpack2(g, glo, ghi);
                gmin_lo[p] = fminf(gmin_lo[p], glo);
                gmin_hi[p] = fminf(gmin_hi[p], ghi);
            }
        }
    }

    // ---- combine halves: B publishes, A mins + sqrt + sums ----
    if (h == 1) {
        cross[t2][0] = gmin_lo[0];
        cross[t2][1] = gmin_hi[0];
        cross[t2][2] = gmin_lo[1];
        cross[t2][3] = gmin_hi[1];
    }
    __syncthreads();

    float lsum = 0.0f;
    if (h == 0) {
        const float c0 = fminf(gmin_lo[0], cross[t2][0]);
        const float c1 = fminf(gmin_hi[0], cross[t2][1]);
        const float c2 = fminf(gmin_lo[1], cross[t2][2]);
        const float c3 = fminf(gmin_hi[1], cross[t2][3]);
        const float d0 = fmaxf(c0 + sx[0], 1e-12f);
        const float d1 = fmaxf(c1 + sx[1], 1e-12f);
        const float d2 = fmaxf(c2 + sx[2], 1e-12f);
        const float d3 = fmaxf(c3 + sx[3], 1e-12f);
        lsum = sqrtf(d0) + sqrtf(d1) + sqrtf(d2) + sqrtf(d3);
    }

    // ---- block tree reduction over all 512 threads (half B adds 0) ----
    red[t] = lsum;
    __syncthreads();
#pragma unroll
    for (int stride = BLOCK / 2; stride > 0; stride >>= 1) {
        if (t < stride) red[t] += red[t + stride];
        __syncthreads();
    }
    if (t == 0) g_partials[bx] = red[0];
}

__global__ void chamfer_reduce_kernel(float* __restrict__ out) {
    __shared__ float red[GRID];
    const int t = threadIdx.x;
    red[t] = g_partials[t];
    __syncthreads();
#pragma unroll
    for (int stride = GRID / 2; stride > 0; stride >>= 1) {
        if (t < stride) red[t] += red[t + stride];
        __syncthreads();
    }
    if (t == 0) out[0] = red[0] * (1.0f / (2.0f * BATCH * NPTS));
}

extern "C" void kernel_launch(void* const* d_in, const int* in_sizes, int n_in,
                              void* d_out, int out_size) {
    const float* x1 = (const float*)d_in[0];
    const float* x2 = (const float*)d_in[1];
    (void)in_sizes; (void)n_in; (void)out_size;

    // Period-4 launch pattern puts chamfer_min_kernel at global launch
    // index 5 (ncu -s 5 -c 1), so the profile lands on the hot kernel.
    chamfer_pad_kernel<<<1, 32>>>();
    chamfer_min_kernel<<<GRID, BLOCK>>>(x1, x2);
    chamfer_reduce_kernel<<<1, GRID>>>((float*)d_out);
    chamfer_pad_kernel<<<1, 32>>>();
}